// round 1
// baseline (speedup 1.0000x reference)
#include <cuda_runtime.h>
#include <math.h>

// Problem dims (fixed for this problem instance)
#define Bq 8
#define Lq 4096
#define Hq 768
#define Pq 256
#define BLq (Bq * Lq)          // 32768
#define CHUNK 32
#define NC (Lq / CHUNK)        // 128

// ---------------- device scratch (module-load allocations; no cudaMalloc) ---
__device__ float g_Wcat[Hq * 768];             // [H=768, 3P=768]: W_dt | B_re^T | B_im^T
__device__ float g_Ccat[512 * Hq];             // [2P=512, H=768]: C_re^T ; -C_im^T
__device__ float g_Z[(size_t)BLq * 768];       // per (b,l): dt[256] | Bu_re[256] | Bu_im[256]
__device__ float g_X[(size_t)BLq * 512];       // per (b,l): x_re[256] | x_im[256]
__device__ float g_agg[(size_t)Bq * NC * 8 * Pq];  // chunk aggregates (R 2x2, c complex-2)
__device__ float g_sin[(size_t)Bq * NC * 4 * Pq];  // chunk incoming states

// ---------------- weight packing ------------------------------------------
__global__ void pack_kernel(const float* __restrict__ Wdt,
                            const float* __restrict__ Bre,
                            const float* __restrict__ Bim,
                            const float* __restrict__ Cre,
                            const float* __restrict__ Cim)
{
    int i = blockIdx.x * blockDim.x + threadIdx.x;
    if (i < Hq * 768) {
        int h = i / 768, j = i % 768;
        float v;
        if (j < 256)      v = Wdt[h * 256 + j];            // W_dt[h, j]
        else if (j < 512) v = Bre[(j - 256) * Hq + h];     // B_re[p, h]
        else              v = Bim[(j - 512) * Hq + h];     // B_im[p, h]
        g_Wcat[i] = v;
    }
    if (i < 512 * Hq) {
        int k = i / 768, h = i % 768;
        float v;
        if (k < 256) v =  Cre[h * 256 + k];                //  C_re[h, p]
        else         v = -Cim[h * 256 + (k - 256)];        // -C_im[h, p]
        g_Ccat[i] = v;
    }
}

// ---------------- fp32 tiled GEMM -----------------------------------------
// C[M, 768] = A[M, KDIM] * Bm[KDIM, 768-ld]  (N covered = 768 via grid.x)
// MODE 0: sigmoid epilogue on cols < 256 (dt), rest raw (Bu).
// MODE 1: add D[col] * U[row, col] (final output).
template <int KDIM, int MODE>
__global__ __launch_bounds__(256)
void gemm_kernel(const float* __restrict__ A, const float* __restrict__ Bm,
                 float* __restrict__ C, const float* __restrict__ Dvec,
                 const float* __restrict__ U)
{
    constexpr int BM = 128, BN = 64, BK = 16;
    __shared__ float As[BK][BM + 4];   // [k][m], +4 pad keeps 16B alignment
    __shared__ float Bs[BK][BN];       // [k][n]

    const int tid  = threadIdx.x;
    const int trow = tid >> 4;         // 0..15 (M direction, 8 rows each)
    const int tcol = tid & 15;         // 0..15 (N direction, 4 cols each)
    const int m0 = blockIdx.y * BM;
    const int n0 = blockIdx.x * BN;

    float acc[8][4] = {};

    for (int k0 = 0; k0 < KDIM; k0 += BK) {
        // load A tile (128x16): 2 float4 per thread, transpose into As[k][m]
#pragma unroll
        for (int r = 0; r < 2; r++) {
            int idx = tid + r * 256;
            int row = idx >> 2, kq = idx & 3;
            float4 v = *(const float4*)(A + (size_t)(m0 + row) * KDIM + (k0 + kq * 4));
            As[kq * 4 + 0][row] = v.x;
            As[kq * 4 + 1][row] = v.y;
            As[kq * 4 + 2][row] = v.z;
            As[kq * 4 + 3][row] = v.w;
        }
        // load B tile (16x64): 1 float4 per thread
        {
            int row = tid >> 4, nq = tid & 15;
            *(float4*)&Bs[row][nq * 4] =
                *(const float4*)(Bm + (size_t)(k0 + row) * 768 + n0 + nq * 4);
        }
        __syncthreads();

#pragma unroll
        for (int kk = 0; kk < BK; kk++) {
            float a[8], b[4];
            *(float4*)&a[0] = *(const float4*)&As[kk][trow * 8];
            *(float4*)&a[4] = *(const float4*)&As[kk][trow * 8 + 4];
            *(float4*)&b[0] = *(const float4*)&Bs[kk][tcol * 4];
#pragma unroll
            for (int i = 0; i < 8; i++)
#pragma unroll
                for (int j = 0; j < 4; j++)
                    acc[i][j] = fmaf(a[i], b[j], acc[i][j]);
        }
        __syncthreads();
    }

    // epilogue
#pragma unroll
    for (int i = 0; i < 8; i++) {
        const int row  = m0 + trow * 8 + i;
        const int col0 = n0 + tcol * 4;
        float4 v = make_float4(acc[i][0], acc[i][1], acc[i][2], acc[i][3]);
        if (MODE == 0) {
            if (col0 < 256) {   // whole float4 is on one side (col0 % 4 == 0)
                v.x = 1.f / (1.f + expf(-v.x));
                v.y = 1.f / (1.f + expf(-v.y));
                v.z = 1.f / (1.f + expf(-v.z));
                v.w = 1.f / (1.f + expf(-v.w));
            }
        } else {
            const float* up = U + (size_t)row * 768 + col0;
            v.x += Dvec[col0 + 0] * up[0];
            v.y += Dvec[col0 + 1] * up[1];
            v.z += Dvec[col0 + 2] * up[2];
            v.w += Dvec[col0 + 3] * up[3];
        }
        *(float4*)(C + (size_t)row * 768 + col0) = v;
    }
}

// ---------------- chunked scan ---------------------------------------------
// Per step: S = 1/(1+dt^2 A); M = S*[[1,-dt*A],[dt,1]]; F = [S*dt*Bu, S*dt^2*Bu]
// (uses M11 = M22 = S identity). State s = complex 2-vector; x = s2.

// Pass A: per-chunk aggregate (R 2x2 real, c complex 2-vector)
__global__ __launch_bounds__(256)
void scan_passA(const float* __restrict__ Adiag)
{
    const int p = threadIdx.x;
    const int chunk = blockIdx.x;
    const int b = blockIdx.y;
    const float Ap = fmaxf(__ldg(&Adiag[p]), 0.f);
    const float* z = g_Z + ((size_t)b * Lq + (size_t)chunk * CHUNK) * 768;

    float r11 = 1.f, r12 = 0.f, r21 = 0.f, r22 = 1.f;
    float c1r = 0.f, c1i = 0.f, c2r = 0.f, c2i = 0.f;
#pragma unroll 4
    for (int t = 0; t < CHUNK; t++) {
        float dt  = z[(size_t)t * 768 + p];
        float bur = z[(size_t)t * 768 + 256 + p];
        float bui = z[(size_t)t * 768 + 512 + p];
        float S   = 1.f / (1.f + dt * dt * Ap);
        float m12 = -dt * Ap * S;
        float m21 = dt * S;
        float n11 = S * r11 + m12 * r21;
        float n12 = S * r12 + m12 * r22;
        float n21 = m21 * r11 + S * r21;
        float n22 = m21 * r12 + S * r22;
        r11 = n11; r12 = n12; r21 = n21; r22 = n22;
        float f1r = S * dt * bur, f1i = S * dt * bui;
        float f2r = dt * f1r,     f2i = dt * f1i;
        float t1r = S * c1r + m12 * c2r + f1r;
        float t1i = S * c1i + m12 * c2i + f1i;
        float t2r = m21 * c1r + S * c2r + f2r;
        float t2i = m21 * c1i + S * c2i + f2i;
        c1r = t1r; c1i = t1i; c2r = t2r; c2i = t2i;
    }
    float* o = g_agg + ((size_t)(b * NC + chunk) * 8) * Pq + p;
    o[0 * Pq] = r11; o[1 * Pq] = r12; o[2 * Pq] = r21; o[3 * Pq] = r22;
    o[4 * Pq] = c1r; o[5 * Pq] = c1i; o[6 * Pq] = c2r; o[7 * Pq] = c2i;
}

// Mid scan: sequential over NC chunk aggregates, store each chunk's incoming state
__global__ __launch_bounds__(256)
void scan_mid()
{
    const int p = threadIdx.x;
    const int b = blockIdx.x;
    float s1r = 0.f, s1i = 0.f, s2r = 0.f, s2i = 0.f;
#pragma unroll 4
    for (int k = 0; k < NC; k++) {
        float* so = g_sin + ((size_t)(b * NC + k) * 4) * Pq + p;
        so[0 * Pq] = s1r; so[1 * Pq] = s1i; so[2 * Pq] = s2r; so[3 * Pq] = s2i;
        const float* a = g_agg + ((size_t)(b * NC + k) * 8) * Pq + p;
        float r11 = a[0 * Pq], r12 = a[1 * Pq], r21 = a[2 * Pq], r22 = a[3 * Pq];
        float c1r = a[4 * Pq], c1i = a[5 * Pq], c2r = a[6 * Pq], c2i = a[7 * Pq];
        float n1r = r11 * s1r + r12 * s2r + c1r;
        float n1i = r11 * s1i + r12 * s2i + c1i;
        float n2r = r21 * s1r + r22 * s2r + c2r;
        float n2i = r21 * s1i + r22 * s2i + c2i;
        s1r = n1r; s1i = n1i; s2r = n2r; s2i = n2i;
    }
}

// Pass B: replay chunk from incoming state, emit x = s2 into X = [x_re | x_im]
__global__ __launch_bounds__(256)
void scan_passB(const float* __restrict__ Adiag)
{
    const int p = threadIdx.x;
    const int chunk = blockIdx.x;
    const int b = blockIdx.y;
    const float Ap = fmaxf(__ldg(&Adiag[p]), 0.f);
    const size_t l0 = (size_t)b * Lq + (size_t)chunk * CHUNK;
    const float* z = g_Z + l0 * 768;
    float* xo = g_X + l0 * 512;
    const float* si = g_sin + ((size_t)(b * NC + chunk) * 4) * Pq + p;
    float s1r = si[0 * Pq], s1i = si[1 * Pq], s2r = si[2 * Pq], s2i = si[3 * Pq];
#pragma unroll 4
    for (int t = 0; t < CHUNK; t++) {
        float dt  = z[(size_t)t * 768 + p];
        float bur = z[(size_t)t * 768 + 256 + p];
        float bui = z[(size_t)t * 768 + 512 + p];
        float S   = 1.f / (1.f + dt * dt * Ap);
        float m12 = -dt * Ap * S;
        float m21 = dt * S;
        float f1r = S * dt * bur, f1i = S * dt * bui;
        float f2r = dt * f1r,     f2i = dt * f1i;
        float n1r = S * s1r + m12 * s2r + f1r;
        float n1i = S * s1i + m12 * s2i + f1i;
        float n2r = m21 * s1r + S * s2r + f2r;
        float n2i = m21 * s1i + S * s2i + f2i;
        s1r = n1r; s1i = n1i; s2r = n2r; s2i = n2i;
        xo[(size_t)t * 512 + p]       = s2r;
        xo[(size_t)t * 512 + 256 + p] = s2i;
    }
}

// ---------------- launch ----------------------------------------------------
extern "C" void kernel_launch(void* const* d_in, const int* in_sizes, int n_in,
                              void* d_out, int out_size)
{
    const float* u      = (const float*)d_in[0];
    const float* A_diag = (const float*)d_in[1];
    const float* B_re   = (const float*)d_in[2];
    const float* B_im   = (const float*)d_in[3];
    const float* C_re   = (const float*)d_in[4];
    const float* C_im   = (const float*)d_in[5];
    const float* Dv     = (const float*)d_in[6];
    const float* W_dt   = (const float*)d_in[7];
    float* y = (float*)d_out;

    float *pW = nullptr, *pC = nullptr, *pZ = nullptr, *pX = nullptr;
    cudaGetSymbolAddress((void**)&pW, g_Wcat);
    cudaGetSymbolAddress((void**)&pC, g_Ccat);
    cudaGetSymbolAddress((void**)&pZ, g_Z);
    cudaGetSymbolAddress((void**)&pX, g_X);

    pack_kernel<<<(Hq * 768 + 255) / 256, 256>>>(W_dt, B_re, B_im, C_re, C_im);

    // GEMM-1: Z = u @ Wcat, sigmoid on dt block.  M=32768, N=768, K=768
    gemm_kernel<768, 0><<<dim3(12, BLq / 128), 256>>>(u, pW, pZ, nullptr, nullptr);

    // chunked scan along L
    scan_passA<<<dim3(NC, Bq), 256>>>(A_diag);
    scan_mid<<<Bq, 256>>>();
    scan_passB<<<dim3(NC, Bq), 256>>>(A_diag);

    // GEMM-2: y = X @ Ccat + D .* u.  M=32768, N=768, K=512
    gemm_kernel<512, 1><<<dim3(12, BLq / 128), 256>>>(pX, pC, y, Dv, u);
}

// round 5
// speedup vs baseline: 1.8979x; 1.8979x over previous
#include <cuda_runtime.h>
#include <cuda_bf16.h>
#include <math.h>
#include <stdint.h>
#include <string.h>

// Problem dims (fixed)
#define Bq 8
#define Lq 4096
#define Hq 768
#define Pq 256
#define BLq (Bq * Lq)          // 32768
#define CHUNK 32
#define NC (Lq / CHUNK)        // 128

// ---------------- device scratch (static globals; no runtime alloc) --------
__device__ __align__(16) float         g_Z[(size_t)BLq * 768];   // dt | Bu_re | Bu_im
__device__ __align__(16) __nv_bfloat16 g_Uhi[(size_t)BLq * 768];
__device__ __align__(16) __nv_bfloat16 g_Ulo[(size_t)BLq * 768];
__device__ __align__(16) __nv_bfloat16 g_Xhi[(size_t)BLq * 512];
__device__ __align__(16) __nv_bfloat16 g_Xlo[(size_t)BLq * 512];
__device__ __align__(16) __nv_bfloat16 g_W1hi[768 * 768], g_W1lo[768 * 768]; // [n][k=H]
__device__ __align__(16) __nv_bfloat16 g_W2hi[768 * 512], g_W2lo[768 * 512]; // [n=h][k=2P]
__device__ __align__(16) float g_agg[(size_t)Bq * NC * 8 * Pq];
__device__ __align__(16) float g_sin[(size_t)Bq * NC * 4 * Pq];

// ---------------- PTX helpers (sm_80-era only: cp.async / ldmatrix / mma) ---
__device__ __forceinline__ uint32_t smem_u32(const void* p) {
    uint32_t a;
    asm("{ .reg .u64 t; cvta.to.shared.u64 t, %1; cvt.u32.u64 %0, t; }" : "=r"(a) : "l"(p));
    return a;
}
#define CP16(dst, src)  asm volatile("cp.async.cg.shared.global [%0], [%1], 16;" :: "r"(dst), "l"(src))
#define CP_COMMIT()     asm volatile("cp.async.commit_group;" ::: "memory")
#define CP_WAIT0()      asm volatile("cp.async.wait_group 0;" ::: "memory")

#define LDSM4(R, addr) \
    asm volatile("ldmatrix.sync.aligned.m8n8.x4.shared.b16 {%0,%1,%2,%3}, [%4];" \
        : "=r"((R)[0]), "=r"((R)[1]), "=r"((R)[2]), "=r"((R)[3]) : "r"(addr))

#define MMA16816(c, a, b0, b1) \
    asm volatile("mma.sync.aligned.m16n8k16.row.col.f32.bf16.bf16.f32 " \
        "{%0,%1,%2,%3},{%4,%5,%6,%7},{%8,%9},{%0,%1,%2,%3};" \
        : "+f"((c)[0]), "+f"((c)[1]), "+f"((c)[2]), "+f"((c)[3]) \
        : "r"((a)[0]), "r"((a)[1]), "r"((a)[2]), "r"((a)[3]), "r"(b0), "r"(b1))

// ---------------- weight packing + split ------------------------------------
__global__ void pack_weights(const float* __restrict__ Wdt,
                             const float* __restrict__ Bre,
                             const float* __restrict__ Bim,
                             const float* __restrict__ Cre,
                             const float* __restrict__ Cim)
{
    int i = blockIdx.x * blockDim.x + threadIdx.x;
    if (i < 768 * 768) {               // W1[n][k]
        int n = i / 768, k = i % 768;
        float v;
        if (n < 256)      v = Wdt[k * 256 + n];
        else if (n < 512) v = Bre[(n - 256) * 768 + k];
        else              v = Bim[(n - 512) * 768 + k];
        __nv_bfloat16 h = __float2bfloat16_rn(v);
        g_W1hi[i] = h;
        g_W1lo[i] = __float2bfloat16_rn(v - __bfloat162float(h));
    }
    if (i < 768 * 512) {               // W2[n=h][k]
        int n = i / 512, k = i % 512;
        float v = (k < 256) ? Cre[n * 256 + k] : -Cim[n * 256 + (k - 256)];
        __nv_bfloat16 h = __float2bfloat16_rn(v);
        g_W2hi[i] = h;
        g_W2lo[i] = __float2bfloat16_rn(v - __bfloat162float(h));
    }
}

// split u -> bf16 hi/lo (8 elems / thread)
__global__ void convert_u(const float* __restrict__ u)
{
    size_t i = ((size_t)blockIdx.x * blockDim.x + threadIdx.x) * 8;
    float f[8];
    *(float4*)&f[0] = *(const float4*)(u + i);
    *(float4*)&f[4] = *(const float4*)(u + i + 4);
    __nv_bfloat16 h[8], l[8];
#pragma unroll
    for (int t = 0; t < 8; t++) {
        h[t] = __float2bfloat16_rn(f[t]);
        l[t] = __float2bfloat16_rn(f[t] - __bfloat162float(h[t]));
    }
    *(uint4*)(g_Uhi + i) = *(uint4*)h;
    *(uint4*)(g_Ulo + i) = *(uint4*)l;
}

// ---------------- mma.sync split-bf16 GEMM ----------------------------------
// C[M,768] = A[M,KDIM] * W[N,KDIM]^T  via  Ah*Bh + Al*Bh + Ah*Bl  (fp32 acc)
// CTA tile 128x256, BK=32, 8 warps (warp tile 64x64), 2-stage cp.async.
// Smem rows have 80B pitch -> (5r+g) mod 8 permutation = conflict-free ldmatrix.
// MODE 0: sigmoid on n0==0 block (dt cols). MODE 1: += D[col]*U[row,col].
template <int KDIM, int MODE>
__global__ __launch_bounds__(256)
void gemm_mma(const __nv_bfloat16* __restrict__ Ahi, const __nv_bfloat16* __restrict__ Alo,
              const __nv_bfloat16* __restrict__ Bhi, const __nv_bfloat16* __restrict__ Blo,
              float* __restrict__ Cout, const float* __restrict__ Dvec,
              const float* __restrict__ U)
{
    extern __shared__ char smem[];
    constexpr int NIT = KDIM / 32;
    constexpr uint32_t ASZ = 128 * 80;                 // 10240
    constexpr uint32_t BSZ = 256 * 80;                 // 20480
    constexpr uint32_t AH = 0, AL = ASZ, BH = 2 * ASZ, BL = 2 * ASZ + BSZ;
    constexpr uint32_t STG = 2 * ASZ + 2 * BSZ;        // 61440 per stage, 2 stages

    const uint32_t sb = smem_u32(smem);
    const int tid = threadIdx.x;
    const int wid = tid >> 5, l = tid & 31;
    const int wm = wid & 1, wn = wid >> 1;             // warp grid 2(M) x 4(N)
    const int m0 = blockIdx.y * 128;
    const int n0 = blockIdx.x * 256;

    auto ld_stage = [&](int it, int s) {
        const uint32_t tb = sb + (uint32_t)s * STG;
        const int k0 = it * 32;
#pragma unroll
        for (int j = 0; j < 2; j++) {                  // A hi+lo: 512 granules each half
            int idx = tid + j * 256;
            int r = idx >> 2, g = idx & 3;
            size_t go = (size_t)(m0 + r) * KDIM + k0 + g * 8;
            uint32_t so = (uint32_t)r * 80 + (uint32_t)g * 16;
            CP16(tb + AH + so, Ahi + go);
            CP16(tb + AL + so, Alo + go);
        }
#pragma unroll
        for (int j = 0; j < 4; j++) {                  // B hi+lo: 1024 granules each
            int idx = tid + j * 256;
            int r = idx >> 2, g = idx & 3;
            size_t go = (size_t)(n0 + r) * KDIM + k0 + g * 8;
            uint32_t so = (uint32_t)r * 80 + (uint32_t)g * 16;
            CP16(tb + BH + so, Bhi + go);
            CP16(tb + BL + so, Blo + go);
        }
    };

    float acc[4][8][4];
#pragma unroll
    for (int mi = 0; mi < 4; mi++)
#pragma unroll
        for (int nt = 0; nt < 8; nt++)
#pragma unroll
            for (int e = 0; e < 4; e++) acc[mi][nt][e] = 0.f;

    ld_stage(0, 0); CP_COMMIT();

    // lane-invariant address bases
    const uint32_t aro = (uint32_t)(wm * 64 + (l & 15)) * 80 + (uint32_t)((l >> 4) * 16);
    const uint32_t bro = (uint32_t)(wn * 64 + (l & 7) + ((l >> 4) * 8)) * 80
                       + (uint32_t)(((l >> 3) & 1) * 16);

    for (int i = 0; i < NIT; i++) {
        CP_WAIT0();                     // chunk i landed in stage i&1
        __syncthreads();                // all warps done reading stage (i+1)&1 (iter i-1)
        if (i + 1 < NIT) { ld_stage(i + 1, (i + 1) & 1); CP_COMMIT(); }
        const uint32_t tb = sb + (uint32_t)(i & 1) * STG;
#pragma unroll
        for (int ks = 0; ks < 2; ks++) {
            const uint32_t ka = tb + aro + (uint32_t)ks * 32;
            const uint32_t kb = tb + bro + (uint32_t)ks * 32;
            uint32_t ah[4][4], al[4][4], bh[4][4], bl[4][4];
            // pass 1: Ah x Bh
#pragma unroll
            for (int mi = 0; mi < 4; mi++) LDSM4(ah[mi], ka + AH + (uint32_t)mi * 1280);
#pragma unroll
            for (int nj = 0; nj < 4; nj++) LDSM4(bh[nj], kb + BH + (uint32_t)nj * 1280);
#pragma unroll
            for (int mi = 0; mi < 4; mi++)
#pragma unroll
                for (int nt = 0; nt < 8; nt++)
                    MMA16816(acc[mi][nt], ah[mi], bh[nt >> 1][2 * (nt & 1)], bh[nt >> 1][2 * (nt & 1) + 1]);
            // pass 2: Al x Bh (bh dies after this)
#pragma unroll
            for (int mi = 0; mi < 4; mi++) LDSM4(al[mi], ka + AL + (uint32_t)mi * 1280);
#pragma unroll
            for (int mi = 0; mi < 4; mi++)
#pragma unroll
                for (int nt = 0; nt < 8; nt++)
                    MMA16816(acc[mi][nt], al[mi], bh[nt >> 1][2 * (nt & 1)], bh[nt >> 1][2 * (nt & 1) + 1]);
            // pass 3: Ah x Bl
#pragma unroll
            for (int nj = 0; nj < 4; nj++) LDSM4(bl[nj], kb + BL + (uint32_t)nj * 1280);
#pragma unroll
            for (int mi = 0; mi < 4; mi++)
#pragma unroll
                for (int nt = 0; nt < 8; nt++)
                    MMA16816(acc[mi][nt], ah[mi], bl[nt >> 1][2 * (nt & 1)], bl[nt >> 1][2 * (nt & 1) + 1]);
        }
    }

    // epilogue: direct stores (c0,c1)@(r0,col) (c2,c3)@(r0+8,col)
#pragma unroll
    for (int mi = 0; mi < 4; mi++) {
        const int r0 = m0 + wm * 64 + mi * 16 + (l >> 2);
#pragma unroll
        for (int nt = 0; nt < 8; nt++) {
            const int col = n0 + wn * 64 + nt * 8 + 2 * (l & 3);
            float v0 = acc[mi][nt][0], v1 = acc[mi][nt][1];
            float v2 = acc[mi][nt][2], v3 = acc[mi][nt][3];
            if (MODE == 0) {
                if (n0 == 0) {
                    v0 = 1.f / (1.f + __expf(-v0));
                    v1 = 1.f / (1.f + __expf(-v1));
                    v2 = 1.f / (1.f + __expf(-v2));
                    v3 = 1.f / (1.f + __expf(-v3));
                }
            } else {
                float d0 = __ldg(&Dvec[col]), d1 = __ldg(&Dvec[col + 1]);
                const float* u0 = U + (size_t)r0 * 768 + col;
                const float* u1 = U + (size_t)(r0 + 8) * 768 + col;
                v0 += d0 * u0[0]; v1 += d1 * u0[1];
                v2 += d0 * u1[0]; v3 += d1 * u1[1];
            }
            *(float2*)(Cout + (size_t)r0 * 768 + col)       = make_float2(v0, v1);
            *(float2*)(Cout + (size_t)(r0 + 8) * 768 + col) = make_float2(v2, v3);
        }
    }
}

// ---------------- chunked scan ----------------------------------------------
__global__ __launch_bounds__(256)
void scan_passA(const float* __restrict__ Adiag)
{
    const int p = threadIdx.x;
    const int chunk = blockIdx.x, b = blockIdx.y;
    const float Ap = fmaxf(__ldg(&Adiag[p]), 0.f);
    const float* z = g_Z + ((size_t)b * Lq + (size_t)chunk * CHUNK) * 768;

    float r11 = 1.f, r12 = 0.f, r21 = 0.f, r22 = 1.f;
    float c1r = 0.f, c1i = 0.f, c2r = 0.f, c2i = 0.f;
#pragma unroll 4
    for (int t = 0; t < CHUNK; t++) {
        float dt  = z[(size_t)t * 768 + p];
        float bur = z[(size_t)t * 768 + 256 + p];
        float bui = z[(size_t)t * 768 + 512 + p];
        float S   = 1.f / (1.f + dt * dt * Ap);
        float m12 = -dt * Ap * S;
        float m21 = dt * S;
        float n11 = S * r11 + m12 * r21, n12 = S * r12 + m12 * r22;
        float n21 = m21 * r11 + S * r21, n22 = m21 * r12 + S * r22;
        r11 = n11; r12 = n12; r21 = n21; r22 = n22;
        float f1r = S * dt * bur, f1i = S * dt * bui;
        float f2r = dt * f1r,     f2i = dt * f1i;
        float t1r = S * c1r + m12 * c2r + f1r;
        float t1i = S * c1i + m12 * c2i + f1i;
        float t2r = m21 * c1r + S * c2r + f2r;
        float t2i = m21 * c1i + S * c2i + f2i;
        c1r = t1r; c1i = t1i; c2r = t2r; c2i = t2i;
    }
    float* o = g_agg + ((size_t)(b * NC + chunk) * 8) * Pq + p;
    o[0 * Pq] = r11; o[1 * Pq] = r12; o[2 * Pq] = r21; o[3 * Pq] = r22;
    o[4 * Pq] = c1r; o[5 * Pq] = c1i; o[6 * Pq] = c2r; o[7 * Pq] = c2i;
}

// mid-scan with batched prefetch (8 iterations' aggregates in flight)
__global__ __launch_bounds__(256)
void scan_mid()
{
    const int p = threadIdx.x;
    const int b = blockIdx.x;
    float s1r = 0.f, s1i = 0.f, s2r = 0.f, s2i = 0.f;
    for (int kb = 0; kb < NC; kb += 8) {
        float a[8][8];
#pragma unroll
        for (int j = 0; j < 8; j++) {
            const float* q = g_agg + ((size_t)(b * NC + kb + j) * 8) * Pq + p;
#pragma unroll
            for (int t = 0; t < 8; t++) a[j][t] = q[(size_t)t * Pq];
        }
#pragma unroll
        for (int j = 0; j < 8; j++) {
            float* so = g_sin + ((size_t)(b * NC + kb + j) * 4) * Pq + p;
            so[0 * Pq] = s1r; so[1 * Pq] = s1i; so[2 * Pq] = s2r; so[3 * Pq] = s2i;
            float n1r = a[j][0] * s1r + a[j][1] * s2r + a[j][4];
            float n1i = a[j][0] * s1i + a[j][1] * s2i + a[j][5];
            float n2r = a[j][2] * s1r + a[j][3] * s2r + a[j][6];
            float n2i = a[j][2] * s1i + a[j][3] * s2i + a[j][7];
            s1r = n1r; s1i = n1i; s2r = n2r; s2i = n2i;
        }
    }
}

// replay chunk, emit x = s2 as bf16 hi/lo (A operand of GEMM-2)
__global__ __launch_bounds__(256)
void scan_passB(const float* __restrict__ Adiag)
{
    const int p = threadIdx.x;
    const int chunk = blockIdx.x, b = blockIdx.y;
    const float Ap = fmaxf(__ldg(&Adiag[p]), 0.f);
    const size_t l0 = (size_t)b * Lq + (size_t)chunk * CHUNK;
    const float* z = g_Z + l0 * 768;
    __nv_bfloat16* xh = g_Xhi + l0 * 512;
    __nv_bfloat16* xl = g_Xlo + l0 * 512;
    const float* si = g_sin + ((size_t)(b * NC + chunk) * 4) * Pq + p;
    float s1r = si[0 * Pq], s1i = si[1 * Pq], s2r = si[2 * Pq], s2i = si[3 * Pq];
#pragma unroll 4
    for (int t = 0; t < CHUNK; t++) {
        float dt  = z[(size_t)t * 768 + p];
        float bur = z[(size_t)t * 768 + 256 + p];
        float bui = z[(size_t)t * 768 + 512 + p];
        float S   = 1.f / (1.f + dt * dt * Ap);
        float m12 = -dt * Ap * S;
        float m21 = dt * S;
        float f1r = S * dt * bur, f1i = S * dt * bui;
        float f2r = dt * f1r,     f2i = dt * f1i;
        float n1r = S * s1r + m12 * s2r + f1r;
        float n1i = S * s1i + m12 * s2i + f1i;
        float n2r = m21 * s1r + S * s2r + f2r;
        float n2i = m21 * s1i + S * s2i + f2i;
        s1r = n1r; s1i = n1i; s2r = n2r; s2i = n2i;
        __nv_bfloat16 hr  = __float2bfloat16_rn(s2r);
        __nv_bfloat16 hi2 = __float2bfloat16_rn(s2i);
        xh[(size_t)t * 512 + p]       = hr;
        xh[(size_t)t * 512 + 256 + p] = hi2;
        xl[(size_t)t * 512 + p]       = __float2bfloat16_rn(s2r - __bfloat162float(hr));
        xl[(size_t)t * 512 + 256 + p] = __float2bfloat16_rn(s2i - __bfloat162float(hi2));
    }
}

// ---------------- launch -----------------------------------------------------
extern "C" void kernel_launch(void* const* d_in, const int* in_sizes, int n_in,
                              void* d_out, int out_size)
{
    const float* u      = (const float*)d_in[0];
    const float* A_diag = (const float*)d_in[1];
    const float* B_re   = (const float*)d_in[2];
    const float* B_im   = (const float*)d_in[3];
    const float* C_re   = (const float*)d_in[4];
    const float* C_im   = (const float*)d_in[5];
    const float* Dv     = (const float*)d_in[6];
    const float* W_dt   = (const float*)d_in[7];
    float* y = (float*)d_out;

    __nv_bfloat16 *pUhi, *pUlo, *pXhi, *pXlo, *pW1hi, *pW1lo, *pW2hi, *pW2lo;
    float* pZ;
    cudaGetSymbolAddress((void**)&pZ, g_Z);
    cudaGetSymbolAddress((void**)&pUhi, g_Uhi);
    cudaGetSymbolAddress((void**)&pUlo, g_Ulo);
    cudaGetSymbolAddress((void**)&pXhi, g_Xhi);
    cudaGetSymbolAddress((void**)&pXlo, g_Xlo);
    cudaGetSymbolAddress((void**)&pW1hi, g_W1hi);
    cudaGetSymbolAddress((void**)&pW1lo, g_W1lo);
    cudaGetSymbolAddress((void**)&pW2hi, g_W2hi);
    cudaGetSymbolAddress((void**)&pW2lo, g_W2lo);

    const int SMEM_BYTES = 2 * 61440;                  // 122880
    cudaFuncSetAttribute(gemm_mma<768, 0>, cudaFuncAttributeMaxDynamicSharedMemorySize, SMEM_BYTES);
    cudaFuncSetAttribute(gemm_mma<512, 1>, cudaFuncAttributeMaxDynamicSharedMemorySize, SMEM_BYTES);

    pack_weights<<<(768 * 768 + 255) / 256, 256>>>(W_dt, B_re, B_im, C_re, C_im);
    convert_u<<<(BLq * 768 / 8 + 255) / 256, 256>>>(u);

    // GEMM-1: Z = u @ [Wdt|Bre^T|Bim^T], sigmoid on dt block
    gemm_mma<768, 0><<<dim3(3, BLq / 128), 256, SMEM_BYTES>>>(
        pUhi, pUlo, pW1hi, pW1lo, pZ, nullptr, nullptr);

    scan_passA<<<dim3(NC, Bq), 256>>>(A_diag);
    scan_mid<<<Bq, 256>>>();
    scan_passB<<<dim3(NC, Bq), 256>>>(A_diag);

    // GEMM-2: y = X @ [Cre^T; -Cim^T] + D.*u
    gemm_mma<512, 1><<<dim3(3, BLq / 128), 256, SMEM_BYTES>>>(
        pXhi, pXlo, pW2hi, pW2lo, y, Dv, u);
}